// round 1
// baseline (speedup 1.0000x reference)
#include <cuda_runtime.h>
#include <cuda_bf16.h>

// Segment-sum of weighted RGB over sorted ray indices.
// pred_rgb[r, c] = sum_{i : ray_indices[i]==r} weights[i] * rgb[i, c]
//
// Inputs (metadata order):
//   d_in[0] rgb_samples     float32 [N_SAMPLES, 3]
//   d_in[1] weights_samples float32 [N_SAMPLES, 1]
//   d_in[2] ray_indices     int32   [N_SAMPLES]   (sorted ascending)
//   d_in[3] n_rays          int32 scalar
// Output: float32 [N_RAYS, 3]

#define IPT 8  // items (samples) per thread; keeps rgb loads 16B-aligned (8*12 = 96)

__global__ void zero_out_kernel(float* __restrict__ out, int n) {
    int i = blockIdx.x * blockDim.x + threadIdx.x;
    if (i < n) out[i] = 0.0f;
}

__global__ __launch_bounds__(256) void integrate_kernel(
    const float4* __restrict__ rgb4,   // 3*N/4 float4
    const float4* __restrict__ w4,     // N/4 float4
    const int4*  __restrict__ idx4,    // N/4 int4
    float* __restrict__ out,
    int n_samples)
{
    int t = blockIdx.x * blockDim.x + threadIdx.x;
    long base = (long)t * IPT;
    if (base >= n_samples) return;

    // ---- vectorized loads: 2x int4 idx, 2x float4 weights, 6x float4 rgb ----
    int4   i0 = idx4[t * 2 + 0];
    int4   i1 = idx4[t * 2 + 1];
    float4 w0 = w4[t * 2 + 0];
    float4 w1 = w4[t * 2 + 1];
    float4 r[6];
#pragma unroll
    for (int k = 0; k < 6; k++) r[k] = rgb4[t * 6 + k];

    const float* rf = reinterpret_cast<const float*>(r);
    int   idx[IPT] = {i0.x, i0.y, i0.z, i0.w, i1.x, i1.y, i1.z, i1.w};
    float w[IPT]   = {w0.x, w0.y, w0.z, w0.w, w1.x, w1.y, w1.z, w1.w};

    // ---- run-length accumulate over sorted indices, flush on change ----
    int cur = idx[0];
    float a0 = 0.f, a1 = 0.f, a2 = 0.f;
#pragma unroll
    for (int k = 0; k < IPT; k++) {
        if (idx[k] != cur) {
            atomicAdd(&out[3 * cur + 0], a0);
            atomicAdd(&out[3 * cur + 1], a1);
            atomicAdd(&out[3 * cur + 2], a2);
            cur = idx[k];
            a0 = a1 = a2 = 0.f;
        }
        a0 = fmaf(w[k], rf[3 * k + 0], a0);
        a1 = fmaf(w[k], rf[3 * k + 1], a1);
        a2 = fmaf(w[k], rf[3 * k + 2], a2);
    }
    atomicAdd(&out[3 * cur + 0], a0);
    atomicAdd(&out[3 * cur + 1], a1);
    atomicAdd(&out[3 * cur + 2], a2);
}

extern "C" void kernel_launch(void* const* d_in, const int* in_sizes, int n_in,
                              void* d_out, int out_size) {
    const float* rgb = (const float*)d_in[0];
    const float* wts = (const float*)d_in[1];
    const int*   idx = (const int*)d_in[2];
    float* out = (float*)d_out;

    int n_samples = in_sizes[2];          // element count of ray_indices

    // zero-init output (poisoned by harness; empty rays must be 0)
    {
        int threads = 256;
        int blocks = (out_size + threads - 1) / threads;
        zero_out_kernel<<<blocks, threads>>>(out, out_size);
    }

    // main segment-sum
    {
        int total_threads = (n_samples + IPT - 1) / IPT;
        int threads = 256;
        int blocks = (total_threads + threads - 1) / threads;
        integrate_kernel<<<blocks, threads>>>(
            (const float4*)rgb, (const float4*)wts, (const int4*)idx,
            out, n_samples);
    }
}